// round 13
// baseline (speedup 1.0000x reference)
#include <cuda_runtime.h>
#include <cuda_bf16.h>
#include <stdint.h>

#define NB 16
#define NN 8192
#define NE 262144
#define ND 8
#define NC 128               // NB*ND columns of the transposed H matrix
#define WPR 256              // words per bitmap row = NN/32
#define NCHG 256             // global 32-k chunks
#define KSPLIT 2
#define NCH 128              // chunks per CTA
#define TILE_B 16384         // one B chunk: 4 ksteps x 8 np x 32 lanes x 16B
#define ONE_BF16X2 0x3F803F80u

// fused-kernel dispatch ranges
#define MMA_CTAS   128
#define DEG_CTAS   128
#define EDGE_CTAS  2048
#define FUSED_CTAS (MMA_CTAS + DEG_CTAS + EDGE_CTAS)

// prep-kernel dispatch ranges
#define CLEAR_CTAS 2048      // NN*WPR/4/256
#define TRANS_CTAS 4096      // NN*NC/256
#define MAKEB_CTAS 2048      // 2^19/256
#define PREP_CTAS  (CLEAR_CTAS + TRANS_CTAS + MAKEB_CTAS)

// ---------------- device scratch (no allocs allowed) ----------------
__device__ uint32_t g_bits[NN * WPR];          // 8 MB adjacency bitmap
__device__ float    g_inv_deg[NN];
__device__ float    g_Ht[NN * NC];             // 4 MB: Ht[k*128 + (b*8+d)] = h[b,k,d]
__device__ uint8_t  g_Bf[NCHG * TILE_B];       // 4 MB: fragment-ordered hi/lo bf16 B
__device__ float    g_part[KSPLIT * NN * NC];  // 8 MB: K-split partials [ks][c][m]
__device__ int      g_is64;

// ---------------- PTX helpers ----------------
__device__ __forceinline__ void mbar_init(uint32_t mbar, uint32_t count) {
    asm volatile("mbarrier.init.shared.b64 [%0], %1;" :: "r"(mbar), "r"(count) : "memory");
}
__device__ __forceinline__ void mbar_expect_tx(uint32_t mbar, uint32_t bytes) {
    asm volatile("mbarrier.arrive.expect_tx.shared.b64 _, [%0], %1;"
                 :: "r"(mbar), "r"(bytes) : "memory");
}
__device__ __forceinline__ void bulk_g2s(uint32_t dst, const void* src, uint32_t bytes, uint32_t mbar) {
    asm volatile("cp.async.bulk.shared::cluster.global.mbarrier::complete_tx::bytes [%0], [%1], %2, [%3];"
                 :: "r"(dst), "l"(src), "r"(bytes), "r"(mbar) : "memory");
}
__device__ __forceinline__ void mbar_wait(uint32_t mbar, uint32_t parity) {
    asm volatile(
        "{\n\t.reg .pred P;\n\t"
        "WAIT_%=:\n\t"
        "mbarrier.try_wait.parity.acquire.cta.shared::cta.b64 P, [%0], %1, 0x989680;\n\t"
        "@!P bra WAIT_%=;\n\t}"
        :: "r"(mbar), "r"(parity) : "memory");
}
__device__ __forceinline__ void mma_bf16(float* c, const uint32_t* a, uint32_t b0, uint32_t b1) {
    asm("mma.sync.aligned.m16n8k16.row.col.f32.bf16.bf16.f32 "
        "{%0,%1,%2,%3}, {%4,%5,%6,%7}, {%8,%9}, {%0,%1,%2,%3};"
        : "+f"(c[0]), "+f"(c[1]), "+f"(c[2]), "+f"(c[3])
        : "r"(a[0]), "r"(a[1]), "r"(a[2]), "r"(a[3]), "r"(b0), "r"(b1));
}

__device__ __forceinline__ int load_idx(const void* p, long long e, bool is64) {
    return is64 ? (int)((const long long*)p)[e] : ((const int*)p)[e];
}

// ---------------- prep: detect + clear + transpose + makeB (fused) ----------------
__global__ __launch_bounds__(256) void k_prep(const float* __restrict__ h,
                                              const void* adj_i) {
    int bid = blockIdx.x;
    int tid = threadIdx.x;

    if (bid == 0 && tid == 0) {
        const int* p = (const int*)adj_i;
        int odd_nonzero = 0;
        #pragma unroll
        for (int t = 0; t < 32; t++)
            if (p[2 * t + 1] != 0) odd_nonzero = 1;
        g_is64 = odd_nonzero ? 0 : 1;
    }

    if (bid < CLEAR_CTAS) {
        int idx = bid * 256 + tid;
        ((uint4*)g_bits)[idx] = make_uint4(0u, 0u, 0u, 0u);
    } else if (bid < CLEAR_CTAS + TRANS_CTAS) {
        int idx = (bid - CLEAR_CTAS) * 256 + tid;     // over NN*NC
        int k = idx >> 7;
        int c = idx & 127;
        int b = c >> 3, d = c & 7;
        g_Ht[idx] = h[((long long)b * NN + k) * ND + d];
    } else {
        int idx = (bid - CLEAR_CTAS - TRANS_CTAS) * 256 + tid;   // 2^19
        int lane = idx & 31;
        int nb   = (idx >> 5) & 15;
        int sl   = (idx >> 9) & 3;
        int gc   = idx >> 11;
        int tg = lane & 3, g = lane >> 2;
        int n  = nb * 8 + g;
        int kb = gc * 32 + sl * 8;
        int b = n >> 3, d = n & 7;
        float v0 = h[((long long)b * NN + (kb + tg)) * ND + d];
        float v1 = h[((long long)b * NN + (kb + 4 + tg)) * ND + d];
        __nv_bfloat16 h0 = __float2bfloat16(v0);
        __nv_bfloat16 l0 = __float2bfloat16(v0 - __bfloat162float(h0));
        __nv_bfloat16 h1 = __float2bfloat16(v1);
        __nv_bfloat16 l1 = __float2bfloat16(v1 - __bfloat162float(h1));
        uint32_t r0 = (uint32_t)__bfloat16_as_ushort(h0) | ((uint32_t)__bfloat16_as_ushort(l0) << 16);
        uint32_t r1 = (uint32_t)__bfloat16_as_ushort(h1) | ((uint32_t)__bfloat16_as_ushort(l1) << 16);
        uint2* dst = (uint2*)(g_Bf + (size_t)gc * TILE_B + sl * 4096
                              + (nb >> 1) * 512 + lane * 16 + (nb & 1) * 8);
        *dst = make_uint2(r0, r1);
    }
}

// ---------------- scatter edges into bitmap (ALL batches) ----------------
__global__ void k_scatter(const void* adj_i, const void* adj_j) {
    long long idx = (long long)blockIdx.x * blockDim.x + threadIdx.x;
    if (idx >= (long long)NB * NE) return;
    bool is64 = g_is64;
    int i = load_idx(adj_i, idx, is64);
    int j = load_idx(adj_j, idx, is64);
    atomicOr(&g_bits[i * WPR + (j >> 5)], 1u << (j & 31));
    atomicOr(&g_bits[j * WPR + (i >> 5)], 1u << (i & 31));
}

// ---------------- fused: MMA GEMM (bid<128) + degree + edge_out ----------------
// bids [0,128):       warp-MMA bitmap GEMM (tensor-bound, wave-1 priority)
// bids [128,256):     degree = popcount+1 (tiny)
// bids [256,2304):    edge_out grid-stride (DRAM-bound, hides under MMA)
__global__ __launch_bounds__(256) void k_fused(
        const float* __restrict__ h,
        const void* adj_i, const void* adj_j,
        const float* __restrict__ W, const float* __restrict__ bias,
        float* __restrict__ edge_out) {
    __shared__ __align__(1024) uint8_t sB[2][TILE_B];        // 32 KB
    __shared__ __align__(8) unsigned long long smbar[2];

    int bid  = blockIdx.x;
    int t    = threadIdx.x;
    int lane = t & 31;
    int w    = t >> 5;

    if (bid < MMA_CTAS) {
        // ======== MMA part (identical to R10 k_mma) ========
        int wr   = w >> 1;
        int wc   = w & 1;
        int tg = lane & 3, g = lane >> 2;

        int ks    = bid & 1;
        int mtile = bid >> 1;
        int rowbase = mtile * 128 + wr * 32;

        const uint32_t* __restrict__ bits = g_bits;
        const uint8_t*  __restrict__ Bsrc = g_Bf + (size_t)ks * NCH * TILE_B;

        uint32_t mb  = (uint32_t)__cvta_generic_to_shared(&smbar[0]);
        uint32_t sb0 = (uint32_t)__cvta_generic_to_shared(&sB[0][0]);

        if (t == 0) {
            mbar_init(mb, 1);
            mbar_init(mb + 8, 1);
            asm volatile("fence.proxy.async.shared::cta;" ::: "memory");
        }
        __syncthreads();
        if (t == 0) {
            mbar_expect_tx(mb, TILE_B);
            bulk_g2s(sb0, Bsrc, TILE_B, mb);
            mbar_expect_tx(mb + 8, TILE_B);
            bulk_g2s(sb0 + TILE_B, Bsrc + TILE_B, TILE_B, mb + 8);
        }

        float acc[2][8][4];
        #pragma unroll
        for (int mt = 0; mt < 2; mt++)
            #pragma unroll
            for (int ni = 0; ni < 8; ni++)
                #pragma unroll
                for (int r = 0; r < 4; r++) acc[mt][ni][r] = 0.0f;

        for (int gc = 0; gc < NCH; gc++) {
            int buf = gc & 1;
            mbar_wait(mb + buf * 8, (gc >> 1) & 1);

            uint32_t wrd = __ldg(&bits[(rowbase + lane) * WPR + ks * NCH + gc]);
            uint32_t wA0 = __shfl_sync(0xffffffffu, wrd, g);
            uint32_t wA1 = __shfl_sync(0xffffffffu, wrd, g + 8);
            uint32_t wA2 = __shfl_sync(0xffffffffu, wrd, g + 16);
            uint32_t wA3 = __shfl_sync(0xffffffffu, wrd, g + 24);

            const uint8_t* base = &sB[buf][0];
            #pragma unroll
            for (int sl = 0; sl < 4; sl++) {
                int p0 = sl * 8 + tg;
                int p1 = p0 + 4;
                uint32_t a[2][4];
                a[0][0] = ((wA0 >> p0) & 1u) * ONE_BF16X2;
                a[0][1] = ((wA1 >> p0) & 1u) * ONE_BF16X2;
                a[0][2] = ((wA0 >> p1) & 1u) * ONE_BF16X2;
                a[0][3] = ((wA1 >> p1) & 1u) * ONE_BF16X2;
                a[1][0] = ((wA2 >> p0) & 1u) * ONE_BF16X2;
                a[1][1] = ((wA3 >> p0) & 1u) * ONE_BF16X2;
                a[1][2] = ((wA2 >> p1) & 1u) * ONE_BF16X2;
                a[1][3] = ((wA3 >> p1) & 1u) * ONE_BF16X2;

                #pragma unroll
                for (int i = 0; i < 4; i++) {
                    uint4 bfr = *(const uint4*)(base + sl * 4096 + (wc * 4 + i) * 512 + lane * 16);
                    #pragma unroll
                    for (int mt = 0; mt < 2; mt++) {
                        mma_bf16(acc[mt][2 * i],     a[mt], bfr.x, bfr.y);
                        mma_bf16(acc[mt][2 * i + 1], a[mt], bfr.z, bfr.w);
                    }
                }
            }

            __syncthreads();
            if (t == 0 && gc + 2 < NCH) {
                mbar_expect_tx(mb + buf * 8, TILE_B);
                bulk_g2s(sb0 + buf * TILE_B, Bsrc + (size_t)(gc + 2) * TILE_B, TILE_B, mb + buf * 8);
            }
        }

        float* part = g_part + (size_t)ks * (NN * NC);
        #pragma unroll
        for (int mt = 0; mt < 2; mt++)
            #pragma unroll
            for (int ni = 0; ni < 8; ni++)
                #pragma unroll
                for (int r = 0; r < 4; r++) {
                    int m = rowbase + mt * 16 + g + ((r >> 1) ? 8 : 0);
                    int n = (wc * 8 + ni) * 8 + 2 * tg + (r & 1);
                    part[(size_t)n * NN + m] = acc[mt][ni][r];
                }
    } else if (bid < MMA_CTAS + DEG_CTAS) {
        // ======== degree part: inv_deg = 1/(popcount(row)+1) ========
        int wid_g = (bid - MMA_CTAS) * 8 + w;       // 0..1023
        #pragma unroll
        for (int it = 0; it < 8; it++) {
            int row = wid_g + it * 1024;
            const uint32_t* wp = &g_bits[row * WPR];
            int cnt = 0;
            #pragma unroll
            for (int tt = 0; tt < WPR / 32; tt++) cnt += __popc(wp[lane + tt * 32]);
            #pragma unroll
            for (int o = 16; o; o >>= 1) cnt += __shfl_xor_sync(0xffffffffu, cnt, o);
            if (lane == 0) g_inv_deg[row] = 1.0f / (float)(cnt + 1);
        }
    } else {
        // ======== edge part: (h[b,ai]+h[b,aj]) @ W^T + bias ========
        float* sW = (float*)&sB[0][0];
        float* sb = sW + 64;
        if (t < 64) sW[t] = W[t];
        if (t < 8)  sb[t] = bias[t];
        __syncthreads();

        bool is64 = g_is64;
        const float4* h4 = (const float4*)h;
        long long base = (long long)(bid - MMA_CTAS - DEG_CTAS) * 256 + t;
        const long long stride = (long long)EDGE_CTAS * 256;

        for (long long idx = base; idx < (long long)NB * NE; idx += stride) {
            int bb = (int)(idx >> 18);
            int e  = (int)(idx & (NE - 1));
            int i = load_idx(adj_i, e, is64);   // batch-0 indices only
            int j = load_idx(adj_j, e, is64);

            long long bi = ((long long)bb * NN + i) * 2;
            long long bj = ((long long)bb * NN + j) * 2;
            float4 x0 = h4[bi], x1 = h4[bi + 1];
            float4 y0 = h4[bj], y1 = h4[bj + 1];
            float s[8] = {x0.x + y0.x, x0.y + y0.y, x0.z + y0.z, x0.w + y0.w,
                          x1.x + y1.x, x1.y + y1.y, x1.z + y1.z, x1.w + y1.w};

            float o[8];
            #pragma unroll
            for (int d = 0; d < 8; d++) {
                float a2 = sb[d];
                #pragma unroll
                for (int k = 0; k < 8; k++) a2 += s[k] * sW[d * 8 + k];
                o[d] = a2;
            }
            float4* out4 = (float4*)(edge_out + idx * 8);
            out4[0] = make_float4(o[0], o[1], o[2], o[3]);
            out4[1] = make_float4(o[4], o[5], o[6], o[7]);
        }
    }
}

// ---------------- combine partials + self + normalize ----------------
__global__ void k_fix(float* __restrict__ out_newh) {
    int idx = blockIdx.x * blockDim.x + threadIdx.x;   // over NN*NC
    int m = idx & (NN - 1);
    int c = idx >> 13;
    float v = (g_part[(size_t)c * NN + m] + g_part[(size_t)(NN * NC) + (size_t)c * NN + m]
               + g_Ht[m * NC + c]) * g_inv_deg[m];
    int b = c >> 3, d = c & 7;
    out_newh[((size_t)b * NN + m) * ND + d] = v;
}

// ---------------- launch ----------------
extern "C" void kernel_launch(void* const* d_in, const int* in_sizes, int n_in,
                              void* d_out, int out_size) {
    const float* h     = (const float*)d_in[0];
    const void*  adj_i = d_in[1];
    const void*  adj_j = d_in[2];
    const float* W     = (const float*)d_in[3];
    const float* bias  = (const float*)d_in[4];
    float* edge_out = (float*)d_out;                                   // (B,E,D)
    float* new_h    = (float*)d_out + (long long)NB * NE * ND;         // (B,N,D)

    k_prep<<<PREP_CTAS, 256>>>(h, adj_i);
    k_scatter<<<(int)(((long long)NB * NE + 255) / 256), 256>>>(adj_i, adj_j);
    k_fused<<<FUSED_CTAS, 256>>>(h, adj_i, adj_j, W, bias, edge_out);
    k_fix<<<(NN * NC) / 256, 256>>>(new_h);
}